// round 5
// baseline (speedup 1.0000x reference)
#include <cuda_runtime.h>

#define DEV_INLINE __device__ __forceinline__

constexpr int NN   = 1024;
constexpr int EE   = 65536;
constexpr int E2   = EE + NN;      // edges + self loops
constexpr int W1O  = 512;          // H*256
constexpr int C1   = 256;
constexpr int W2O  = 128;          // H*64
constexpr int C2   = 64;

// ---------------- scratch (device globals) -------------
__device__ float g_xp[2][NN * W1O];
__device__ float g_h1[NN * W1O];
__device__ float g_att[2 * 2 * NN * 2];   // [rel][als/ald][node*2+head]
__device__ int   g_cnt[2][NN];
__device__ int   g_off[2][NN + 1];
__device__ int   g_cur[2][NN];
__device__ int   g_srcs[2][E2];
__device__ float g_s[NN];

// ---------------- block reduction helpers ----------------
template <int BLOCK>
DEV_INLINE float blockReduceMax(float v, float* red) {
    #pragma unroll
    for (int o = 16; o; o >>= 1) v = fmaxf(v, __shfl_xor_sync(0xffffffffu, v, o));
    int t = threadIdx.x;
    if ((t & 31) == 0) red[t >> 5] = v;
    __syncthreads();
    constexpr int NW = BLOCK / 32;
    if (t < 32) {
        float x = (t < NW) ? red[t] : -1e30f;
        #pragma unroll
        for (int o = 16; o; o >>= 1) x = fmaxf(x, __shfl_xor_sync(0xffffffffu, x, o));
        if (t == 0) red[0] = x;
    }
    __syncthreads();
    float r = red[0];
    __syncthreads();
    return r;
}

template <int BLOCK>
DEV_INLINE float blockReduceSum(float v, float* red) {
    #pragma unroll
    for (int o = 16; o; o >>= 1) v += __shfl_xor_sync(0xffffffffu, v, o);
    int t = threadIdx.x;
    if ((t & 31) == 0) red[t >> 5] = v;
    __syncthreads();
    constexpr int NW = BLOCK / 32;
    if (t < 32) {
        float x = (t < NW) ? red[t] : 0.f;
        #pragma unroll
        for (int o = 16; o; o >>= 1) x += __shfl_xor_sync(0xffffffffu, x, o);
        if (t == 0) red[0] = x;
    }
    __syncthreads();
    float r = red[0];
    __syncthreads();
    return r;
}

// =======================================================================
// FUSED launch: gemm1 (both relations) + attn1 logits (atomic epilogue)
//               + edge counting
// =======================================================================
constexpr int G1_GEMM_BLOCKS  = (W1O / 64) * (NN / 128) * 2;   // 128
constexpr int G1_COUNT_BLOCKS = EE / 4 / 256;                  // 64

__global__ void __launch_bounds__(256)
k_gemm1_count(const float* __restrict__ A,
              const float* __restrict__ B0, const float* __restrict__ B1,
              float* __restrict__ Co0, float* __restrict__ Co1,
              const int* __restrict__ ei0, const int* __restrict__ ei1,
              const float* __restrict__ as0, const float* __restrict__ as1,
              const float* __restrict__ ad0, const float* __restrict__ ad1,
              float* __restrict__ att) {
    int bid = blockIdx.x;
    int t = threadIdx.x;

    if (bid >= G1_GEMM_BLOCKS) {
        int cid = bid - G1_GEMM_BLOCKS;
        int idx = cid * 256 + t;
        int4 d0 = ((const int4*)(ei0 + EE))[idx];
        int4 d1 = ((const int4*)(ei1 + EE))[idx];
        atomicAdd(&g_cnt[0][d0.x], 1); atomicAdd(&g_cnt[0][d0.y], 1);
        atomicAdd(&g_cnt[0][d0.z], 1); atomicAdd(&g_cnt[0][d0.w], 1);
        atomicAdd(&g_cnt[1][d1.x], 1); atomicAdd(&g_cnt[1][d1.y], 1);
        atomicAdd(&g_cnt[1][d1.z], 1); atomicAdd(&g_cnt[1][d1.w], 1);
        return;
    }

    constexpr int K = 256, Nc = W1O;
    __shared__ float4 sh[768];
    float*  As  = (float*)sh;
    float4* As4 = sh;                            // row stride 32
    float4* Bs4 = sh + 512;                      // [16][16]

    int rel = bid >> 6;
    int r   = bid & 63;
    int bn  = (r & 7) * 64;
    int bm  = (r >> 3) * 128;
    const float* B = rel ? B1 : B0;
    float*       C = rel ? Co1 : Co0;

    int tx = t & 15, ty = t >> 4;
    int am = t >> 2, ak = (t & 3) * 4;

    float4 acc[8];
    #pragma unroll
    for (int i = 0; i < 8; i++) acc[i] = make_float4(0.f, 0.f, 0.f, 0.f);

    float4 a_reg0 = *(const float4*)(A + (size_t)(bm + am) * K + ak);
    float4 a_reg1 = *(const float4*)(A + (size_t)(bm + am + 64) * K + ak);
    float4 b_reg  = *(const float4*)(B + (size_t)(t >> 4) * Nc + bn + (t & 15) * 4);

    for (int k0 = 0; k0 < K; k0 += 16) {
        As[(ak + 0) * 128 + am] = a_reg0.x;
        As[(ak + 1) * 128 + am] = a_reg0.y;
        As[(ak + 2) * 128 + am] = a_reg0.z;
        As[(ak + 3) * 128 + am] = a_reg0.w;
        As[(ak + 0) * 128 + am + 64] = a_reg1.x;
        As[(ak + 1) * 128 + am + 64] = a_reg1.y;
        As[(ak + 2) * 128 + am + 64] = a_reg1.z;
        As[(ak + 3) * 128 + am + 64] = a_reg1.w;
        Bs4[(t >> 4) * 16 + (t & 15)] = b_reg;
        __syncthreads();

        if (k0 + 16 < K) {
            a_reg0 = *(const float4*)(A + (size_t)(bm + am) * K + k0 + 16 + ak);
            a_reg1 = *(const float4*)(A + (size_t)(bm + am + 64) * K + k0 + 16 + ak);
            b_reg  = *(const float4*)(B + (size_t)(k0 + 16 + (t >> 4)) * Nc + bn + (t & 15) * 4);
        }

        #pragma unroll
        for (int k = 0; k < 16; k++) {
            float4 a0 = As4[k * 32 + ty * 2];
            float4 a1 = As4[k * 32 + ty * 2 + 1];
            float4 b  = Bs4[k * 16 + tx];
            float ar[8] = {a0.x, a0.y, a0.z, a0.w, a1.x, a1.y, a1.z, a1.w};
            #pragma unroll
            for (int i = 0; i < 8; i++) {
                acc[i].x = fmaf(ar[i], b.x, acc[i].x);
                acc[i].y = fmaf(ar[i], b.y, acc[i].y);
                acc[i].z = fmaf(ar[i], b.z, acc[i].z);
                acc[i].w = fmaf(ar[i], b.w, acc[i].w);
            }
        }
        __syncthreads();
    }
    #pragma unroll
    for (int i = 0; i < 8; i++)
        *(float4*)(C + (size_t)(bm + ty * 8 + i) * Nc + bn + tx * 4) = acc[i];

    // ---- fused attn1 logit partials ----
    const float* asrc = rel ? as1 : as0;
    const float* adst = rel ? ad1 : ad0;
    int h   = bn >> 8;                       // head (C1=256)
    int cin = (bn & 255) + tx * 4;
    float4 avs = *(const float4*)(asrc + h * C1 + cin);
    float4 avd = *(const float4*)(adst + h * C1 + cin);
    float* alsb = att + (rel * 2 + 0) * (NN * 2);
    float* aldb = att + (rel * 2 + 1) * (NN * 2);
    #pragma unroll
    for (int i = 0; i < 8; i++) {
        float ps = acc[i].x * avs.x + acc[i].y * avs.y + acc[i].z * avs.z + acc[i].w * avs.w;
        float pd = acc[i].x * avd.x + acc[i].y * avd.y + acc[i].z * avd.z + acc[i].w * avd.w;
        #pragma unroll
        for (int o = 8; o; o >>= 1) {
            ps += __shfl_xor_sync(0xffffffffu, ps, o);
            pd += __shfl_xor_sync(0xffffffffu, pd, o);
        }
        if (tx == 0) {
            int row = bm + ty * 8 + i;
            atomicAdd(&alsb[row * 2 + h], ps);
            atomicAdd(&aldb[row * 2 + h], pd);
        }
    }
}

// =======================================================================
// scan (adds self loop)
// =======================================================================
__global__ void k_scan() {
    int r = blockIdx.x;
    int t = threadIdx.x;
    __shared__ int sh[NN];
    int mine = g_cnt[r][t] + 1;
    sh[t] = mine;
    __syncthreads();
    #pragma unroll
    for (int d = 1; d < NN; d <<= 1) {
        int v = (t >= d) ? sh[t - d] : 0;
        __syncthreads();
        sh[t] += v;
        __syncthreads();
    }
    g_off[r][t + 1] = sh[t];
    if (t == 0) g_off[r][0] = 0;
    g_cur[r][t] = sh[t] - mine;
}

// =======================================================================
// CSR fill (4 edges/thread)
// =======================================================================
constexpr int FILL_BLOCKS = E2 / 4 / 256;     // 65

__global__ void __launch_bounds__(256)
k_fill(const int* __restrict__ ei0, const int* __restrict__ ei1) {
    int bid = blockIdx.x;
    int t = threadIdx.x;
    int base = bid * 1024 + t * 4;
    if (base < EE) {
        int idx = bid * 256 + t;
        int4 s0 = ((const int4*)ei0)[idx];
        int4 d0 = ((const int4*)(ei0 + EE))[idx];
        int4 s1 = ((const int4*)ei1)[idx];
        int4 d1 = ((const int4*)(ei1 + EE))[idx];
        int p;
        p = atomicAdd(&g_cur[0][d0.x], 1); g_srcs[0][p] = s0.x;
        p = atomicAdd(&g_cur[0][d0.y], 1); g_srcs[0][p] = s0.y;
        p = atomicAdd(&g_cur[0][d0.z], 1); g_srcs[0][p] = s0.z;
        p = atomicAdd(&g_cur[0][d0.w], 1); g_srcs[0][p] = s0.w;
        p = atomicAdd(&g_cur[1][d1.x], 1); g_srcs[1][p] = s1.x;
        p = atomicAdd(&g_cur[1][d1.y], 1); g_srcs[1][p] = s1.y;
        p = atomicAdd(&g_cur[1][d1.z], 1); g_srcs[1][p] = s1.z;
        p = atomicAdd(&g_cur[1][d1.w], 1); g_srcs[1][p] = s1.w;
    } else {
        #pragma unroll
        for (int u = 0; u < 4; u++) {
            int n = base + u - EE;
            int p0 = atomicAdd(&g_cur[0][n], 1); g_srcs[0][p0] = n;
            int p1 = atomicAdd(&g_cur[1][n], 1); g_srcs[1][p1] = n;
        }
    }
}

// =======================================================================
// gemm2 + fused attn2 logit epilogue
// =======================================================================
__global__ void __launch_bounds__(128)
k_gemm2(const float* __restrict__ A,
        const float* __restrict__ B0, const float* __restrict__ B1,
        float* __restrict__ Co0, float* __restrict__ Co1,
        const float* __restrict__ as0, const float* __restrict__ as1,
        const float* __restrict__ ad0, const float* __restrict__ ad1,
        float* __restrict__ att) {
    constexpr int K = 512, Nc = W2O;
    __shared__ float4 sh[384];
    float*  As  = (float*)sh;
    float4* As4 = sh;                            // row stride 16
    float4* Bs4 = sh + 256;                      // [16][8]

    int bid = blockIdx.x;
    int rel = bid >> 6;
    int r   = bid & 63;
    int bn  = (r & 3) * 32;
    int bm  = (r >> 2) * 64;
    const float* B = rel ? B1 : B0;
    float*       C = rel ? Co1 : Co0;

    int t = threadIdx.x;
    int tx = t & 7, ty = t >> 3;
    int am = t >> 2, ak = (t & 3) * 4;

    float4 acc[4];
    #pragma unroll
    for (int i = 0; i < 4; i++) acc[i] = make_float4(0.f, 0.f, 0.f, 0.f);

    float4 a_reg0 = *(const float4*)(A + (size_t)(bm + am) * K + ak);
    float4 a_reg1 = *(const float4*)(A + (size_t)(bm + am + 32) * K + ak);
    float4 b_reg  = *(const float4*)(B + (size_t)(t >> 3) * Nc + bn + (t & 7) * 4);

    for (int k0 = 0; k0 < K; k0 += 16) {
        As[(ak + 0) * 64 + am] = a_reg0.x;
        As[(ak + 1) * 64 + am] = a_reg0.y;
        As[(ak + 2) * 64 + am] = a_reg0.z;
        As[(ak + 3) * 64 + am] = a_reg0.w;
        As[(ak + 0) * 64 + am + 32] = a_reg1.x;
        As[(ak + 1) * 64 + am + 32] = a_reg1.y;
        As[(ak + 2) * 64 + am + 32] = a_reg1.z;
        As[(ak + 3) * 64 + am + 32] = a_reg1.w;
        Bs4[(t >> 3) * 8 + (t & 7)] = b_reg;
        __syncthreads();

        if (k0 + 16 < K) {
            a_reg0 = *(const float4*)(A + (size_t)(bm + am) * K + k0 + 16 + ak);
            a_reg1 = *(const float4*)(A + (size_t)(bm + am + 32) * K + k0 + 16 + ak);
            b_reg  = *(const float4*)(B + (size_t)(k0 + 16 + (t >> 3)) * Nc + bn + (t & 7) * 4);
        }

        #pragma unroll
        for (int k = 0; k < 16; k++) {
            float4 a = As4[k * 16 + ty];
            float4 b = Bs4[k * 8 + tx];
            float ar[4] = {a.x, a.y, a.z, a.w};
            #pragma unroll
            for (int i = 0; i < 4; i++) {
                acc[i].x = fmaf(ar[i], b.x, acc[i].x);
                acc[i].y = fmaf(ar[i], b.y, acc[i].y);
                acc[i].z = fmaf(ar[i], b.z, acc[i].z);
                acc[i].w = fmaf(ar[i], b.w, acc[i].w);
            }
        }
        __syncthreads();
    }
    #pragma unroll
    for (int i = 0; i < 4; i++)
        *(float4*)(C + (size_t)(bm + ty * 4 + i) * Nc + bn + tx * 4) = acc[i];

    // ---- fused attn2 logit partials ----
    const float* asrc = rel ? as1 : as0;
    const float* adst = rel ? ad1 : ad0;
    int h   = bn >> 6;                       // head (C2=64)
    int cin = (bn & 63) + tx * 4;
    float4 avs = *(const float4*)(asrc + h * C2 + cin);
    float4 avd = *(const float4*)(adst + h * C2 + cin);
    float* alsb = att + (rel * 2 + 0) * (NN * 2);
    float* aldb = att + (rel * 2 + 1) * (NN * 2);
    #pragma unroll
    for (int i = 0; i < 4; i++) {
        float ps = acc[i].x * avs.x + acc[i].y * avs.y + acc[i].z * avs.z + acc[i].w * avs.w;
        float pd = acc[i].x * avd.x + acc[i].y * avd.y + acc[i].z * avd.z + acc[i].w * avd.w;
        #pragma unroll
        for (int o = 4; o; o >>= 1) {
            ps += __shfl_xor_sync(0xffffffffu, ps, o);
            pd += __shfl_xor_sync(0xffffffffu, pd, o);
        }
        if (tx == 0) {
            int row = bm + ty * 4 + i;
            atomicAdd(&alsb[row * 2 + h], ps);
            atomicAdd(&aldb[row * 2 + h], pd);
        }
    }
}

// =======================================================================
// fused dst-centric softmax+gather (both relations), float4 gather,
// PAR edges in flight, als staged in shared
// =======================================================================
template <int WOUT, int C, int BLOCK, int PAR, int LAYER>
__global__ void __launch_bounds__(BLOCK)
k_agg(const float* __restrict__ xpA, const float* __restrict__ xpB,
      const float* __restrict__ att,
      const int* __restrict__ off, const int* __restrict__ srcs,
      const float* __restrict__ b0, const float* __restrict__ b1,
      float* __restrict__ h1out, const float* __restrict__ wlin,
      float* __restrict__ sout) {
    constexpr int CH = 512;
    constexpr int TG = BLOCK / PAR;      // threads per edge-group
    static_assert(TG * 4 == WOUT, "layout");

    __shared__ float  sh_als[NN * 2];
    __shared__ int    sh_src[CH];
    __shared__ float  sh_e0[CH];
    __shared__ float  sh_e1[CH];
    __shared__ float4 sh_grp[BLOCK];
    __shared__ float  red[32];

    int dst = blockIdx.x, t = threadIdx.x;
    int grp = t / TG, ct = t % TG;
    int cols = ct * 4;
    int head = (cols >= C) ? 1 : 0;

    float4 tot = make_float4(0.f, 0.f, 0.f, 0.f);

    #pragma unroll
    for (int r = 0; r < 2; r++) {
        const float* xp    = r ? xpB : xpA;
        const float* alsr  = att + (r * 2 + 0) * (NN * 2);
        const float* aldr  = att + (r * 2 + 1) * (NN * 2);
        const int*   offr  = off + (size_t)r * (NN + 1);
        const int*   srcsr = srcs + (size_t)r * E2;

        __syncthreads();
        for (int i = t; i < NN * 2 / 4; i += BLOCK)
            ((float4*)sh_als)[i] = ((const float4*)alsr)[i];
        __syncthreads();

        int o0 = offr[dst], o1 = offr[dst + 1];
        int range = o1 - o0;
        float ad0 = aldr[dst * 2 + 0], ad1 = aldr[dst * 2 + 1];

        // pass 1: per-head max of leaky-relu logits
        float mx0 = -1e30f, mx1 = -1e30f;
        for (int i = t; i < range; i += BLOCK) {
            int s = srcsr[o0 + i];
            float l0 = sh_als[s * 2 + 0] + ad0; l0 = l0 > 0.f ? l0 : 0.2f * l0;
            float l1 = sh_als[s * 2 + 1] + ad1; l1 = l1 > 0.f ? l1 : 0.2f * l1;
            mx0 = fmaxf(mx0, l0);
            mx1 = fmaxf(mx1, l1);
        }
        mx0 = blockReduceMax<BLOCK>(mx0, red);
        mx1 = blockReduceMax<BLOCK>(mx1, red);

        float4 a4 = make_float4(0.f, 0.f, 0.f, 0.f);
        float sum0 = 0.f, sum1 = 0.f;

        for (int base = 0; base < range; base += CH) {
            int nn = min(CH, range - base);
            __syncthreads();
            for (int i = t; i < nn; i += BLOCK) {
                int s = srcsr[o0 + base + i];
                sh_src[i] = s;
                float l0 = sh_als[s * 2 + 0] + ad0; l0 = l0 > 0.f ? l0 : 0.2f * l0;
                float l1 = sh_als[s * 2 + 1] + ad1; l1 = l1 > 0.f ? l1 : 0.2f * l1;
                float e0 = expf(l0 - mx0);
                float e1 = expf(l1 - mx1);
                sh_e0[i] = e0; sh_e1[i] = e1;
                sum0 += e0; sum1 += e1;
            }
            __syncthreads();
            #pragma unroll 4
            for (int j = grp; j < nn; j += PAR) {
                int s = sh_src[j];
                float e = head ? sh_e1[j] : sh_e0[j];
                float4 row = *(const float4*)(xp + (size_t)s * WOUT + cols);
                a4.x = fmaf(e, row.x, a4.x);
                a4.y = fmaf(e, row.y, a4.y);
                a4.z = fmaf(e, row.z, a4.z);
                a4.w = fmaf(e, row.w, a4.w);
            }
        }
        sum0 = blockReduceSum<BLOCK>(sum0, red);
        sum1 = blockReduceSum<BLOCK>(sum1, red);
        float inv = head ? 1.f / (sum1 + 1e-16f) : 1.f / (sum0 + 1e-16f);
        tot.x = fmaf(a4.x, inv, tot.x);
        tot.y = fmaf(a4.y, inv, tot.y);
        tot.z = fmaf(a4.z, inv, tot.z);
        tot.w = fmaf(a4.w, inv, tot.w);
    }

    // merge PAR edge-groups
    sh_grp[t] = tot;
    __syncthreads();
    if (t < TG) {
        float4 v = sh_grp[t];
        #pragma unroll
        for (int p = 1; p < PAR; p++) {
            float4 o = sh_grp[p * TG + t];
            v.x += o.x; v.y += o.y; v.z += o.z; v.w += o.w;
        }
        float4 bv0 = ((const float4*)b0)[t];
        float4 bv1 = ((const float4*)b1)[t];
        v.x += bv0.x + bv1.x;
        v.y += bv0.y + bv1.y;
        v.z += bv0.z + bv1.z;
        v.w += bv0.w + bv1.w;
        if (LAYER == 1) {
            v.x = v.x > 0.f ? v.x : 0.f;
            v.y = v.y > 0.f ? v.y : 0.f;
            v.z = v.z > 0.f ? v.z : 0.f;
            v.w = v.w > 0.f ? v.w : 0.f;
            ((float4*)(h1out + (size_t)dst * WOUT))[t] = v;
        } else {
            float4 wl = ((const float4*)wlin)[t];
            float p = v.x * wl.x + v.y * wl.y + v.z * wl.z + v.w * wl.w;
            #pragma unroll
            for (int o = 16; o; o >>= 1) p += __shfl_xor_sync(0xffffffffu, p, o);
            if (t == 0) sout[dst] = p;
        }
    }
}

// ---------------- pairwise output: out[i*N+j] = s[i]+s[j]+b ----------------
__global__ void k_pair(float* __restrict__ out, const float* __restrict__ blin) {
    int idx = blockIdx.x * blockDim.x + threadIdx.x;
    float b = blin[0];
    int i = idx >> 8;
    int j4 = (idx & 255) << 2;
    float si = g_s[i] + b;
    float4 v;
    v.x = si + g_s[j4 + 0];
    v.y = si + g_s[j4 + 1];
    v.z = si + g_s[j4 + 2];
    v.w = si + g_s[j4 + 3];
    ((float4*)out)[idx] = v;
}

// ---------------- launch ----------------
extern "C" void kernel_launch(void* const* d_in, const int* in_sizes, int n_in,
                              void* d_out, int out_size) {
    const float* x    = (const float*)d_in[0];
    const int*   ei0  = (const int*)d_in[1];
    const int*   ei1  = (const int*)d_in[2];
    const float* W1[2]  = {(const float*)d_in[3],  (const float*)d_in[7]};
    const float* as1[2] = {(const float*)d_in[4],  (const float*)d_in[8]};
    const float* ad1[2] = {(const float*)d_in[5],  (const float*)d_in[9]};
    const float* b1[2]  = {(const float*)d_in[6],  (const float*)d_in[10]};
    const float* W2[2]  = {(const float*)d_in[11], (const float*)d_in[15]};
    const float* as2[2] = {(const float*)d_in[12], (const float*)d_in[16]};
    const float* ad2[2] = {(const float*)d_in[13], (const float*)d_in[17]};
    const float* b2[2]  = {(const float*)d_in[14], (const float*)d_in[18]};
    const float* wlin = (const float*)d_in[19];
    const float* blin = (const float*)d_in[20];
    float* out = (float*)d_out;

    float *xp, *h1, *attp, *sp;
    int *cntp, *offp, *srcsp;
    cudaGetSymbolAddress((void**)&xp,    g_xp);
    cudaGetSymbolAddress((void**)&h1,    g_h1);
    cudaGetSymbolAddress((void**)&attp,  g_att);
    cudaGetSymbolAddress((void**)&cntp,  g_cnt);
    cudaGetSymbolAddress((void**)&offp,  g_off);
    cudaGetSymbolAddress((void**)&srcsp, g_srcs);
    cudaGetSymbolAddress((void**)&sp,    g_s);

    float* xp0 = xp;
    float* xp1 = xp + (size_t)NN * W1O;

    cudaMemsetAsync(cntp, 0, 2 * NN * sizeof(int));
    cudaMemsetAsync(attp, 0, 2 * 2 * NN * 2 * sizeof(float));

    // gemm1 (+attn1 epilogue) + edge count
    k_gemm1_count<<<G1_GEMM_BLOCKS + G1_COUNT_BLOCKS, 256>>>(
        x, W1[0], W1[1], xp0, xp1, ei0, ei1,
        as1[0], as1[1], ad1[0], ad1[1], attp);

    k_scan<<<2, 1024>>>();
    k_fill<<<FILL_BLOCKS, 256>>>(ei0, ei1);

    // layer-1 aggregation (+bias+relu fused)
    k_agg<W1O, C1, 256, 2, 1><<<NN, 256>>>(
        xp0, xp1, attp, offp, srcsp, b1[0], b1[1], h1, nullptr, nullptr);

    cudaMemsetAsync(attp, 0, 2 * 2 * NN * 2 * sizeof(float));

    // gemm2 (+attn2 epilogue)
    k_gemm2<<<128, 128>>>(h1, W2[0], W2[1], xp0, xp1,
                          as2[0], as2[1], ad2[0], ad2[1], attp);

    // layer-2 aggregation (+bias+w_lin fused -> s)
    k_agg<W2O, C2, 128, 4, 2><<<NN, 128>>>(
        xp0, xp1, attp, offp, srcsp, b2[0], b2[1], nullptr, wlin, sp);

    k_pair<<<NN * NN / 4 / 256, 256>>>(out, blin);
}